// round 1
// baseline (speedup 1.0000x reference)
#include <cuda_runtime.h>
#include <math.h>

#define B_   2
#define N_   2048
#define C_   768
#define H_   12
#define HD_  64
#define HID_ 3072
#define C3_  (3 * C_)

// ---------------- scratch (device globals: no allocations allowed) ----------------
__device__ float g_h[(size_t)B_ * N_ * C_];          // LN output (reused for LN1 and LN2)
__device__ float g_qkv[(size_t)B_ * N_ * C3_];       // fused QKV projection
__device__ float g_attn[(size_t)B_ * H_ * N_ * N_];  // attention logits -> probs (400 MB)
__device__ float g_o[(size_t)B_ * N_ * C_];          // attention output, [B,N,H*HD]
__device__ float g_x2[(size_t)B_ * N_ * C_];         // residual after attention
__device__ float g_h3[(size_t)B_ * N_ * HID_];       // FC1 (gelu) output

// ---------------- block reductions ----------------
__device__ __forceinline__ float block_sum256(float v, float* red) {
    #pragma unroll
    for (int o = 16; o; o >>= 1) v += __shfl_xor_sync(0xffffffffu, v, o);
    if ((threadIdx.x & 31) == 0) red[threadIdx.x >> 5] = v;
    __syncthreads();
    if (threadIdx.x < 32) {
        float t = (threadIdx.x < 8) ? red[threadIdx.x] : 0.0f;
        #pragma unroll
        for (int o = 4; o; o >>= 1) t += __shfl_xor_sync(0xffffffffu, t, o);
        if (threadIdx.x == 0) red[0] = t;
    }
    __syncthreads();
    float r = red[0];
    __syncthreads();
    return r;
}

__device__ __forceinline__ float block_max256(float v, float* red) {
    #pragma unroll
    for (int o = 16; o; o >>= 1) v = fmaxf(v, __shfl_xor_sync(0xffffffffu, v, o));
    if ((threadIdx.x & 31) == 0) red[threadIdx.x >> 5] = v;
    __syncthreads();
    if (threadIdx.x < 32) {
        float t = (threadIdx.x < 8) ? red[threadIdx.x] : -1e30f;
        #pragma unroll
        for (int o = 4; o; o >>= 1) t = fmaxf(t, __shfl_xor_sync(0xffffffffu, t, o));
        if (threadIdx.x == 0) red[0] = t;
    }
    __syncthreads();
    float r = red[0];
    __syncthreads();
    return r;
}

// ---------------- LayerNorm: one block (256 thr) per row of 768 ----------------
__global__ void __launch_bounds__(256) ln_kernel(const float* __restrict__ x,
                                                 const float* __restrict__ g,
                                                 const float* __restrict__ b,
                                                 float* __restrict__ out) {
    __shared__ float red[32];
    int row = blockIdx.x;
    const float* xr = x + (size_t)row * C_;
    int t = threadIdx.x;
    float v0 = xr[t], v1 = xr[t + 256], v2 = xr[t + 512];
    float mean = block_sum256(v0 + v1 + v2, red) * (1.0f / C_);
    float d0 = v0 - mean, d1 = v1 - mean, d2 = v2 - mean;
    float var = block_sum256(d0 * d0 + d1 * d1 + d2 * d2, red) * (1.0f / C_);
    float rstd = rsqrtf(var + 1e-5f);
    float* orow = out + (size_t)row * C_;
    orow[t]       = d0 * rstd * g[t]       + b[t];
    orow[t + 256] = d1 * rstd * g[t + 256] + b[t + 256];
    orow[t + 512] = d2 * rstd * g[t + 512] + b[t + 512];
}

// ---------------- generic NT SGEMM: C = A[M,K] @ W[N,K]^T (+epilogue) ----------------
// EPI: 0 = plain, 1 = +bias +residual, 2 = +bias + exact GELU
template <int EPI>
__global__ void __launch_bounds__(256) sgemm_nt(const float* __restrict__ A,
                                                const float* __restrict__ W,
                                                const float* __restrict__ bias,
                                                const float* __restrict__ res,
                                                float* __restrict__ C,
                                                int M, int N, int K) {
    __shared__ float As[16][128];
    __shared__ float Bs[16][128];
    int m0 = blockIdx.y * 128, n0 = blockIdx.x * 128;
    int tid = threadIdx.x;
    int ty = tid >> 4, tx = tid & 15;
    float acc[8][8] = {};
    const float* Ab = A + (size_t)m0 * K;
    const float* Wb = W + (size_t)n0 * K;
    for (int k0 = 0; k0 < K; k0 += 16) {
        #pragma unroll
        for (int l = 0; l < 2; l++) {
            int f = tid + l * 256;
            int r = f >> 2, kq = (f & 3) << 2;
            float4 a = *(const float4*)(Ab + (size_t)r * K + k0 + kq);
            As[kq + 0][r] = a.x; As[kq + 1][r] = a.y; As[kq + 2][r] = a.z; As[kq + 3][r] = a.w;
            float4 w = *(const float4*)(Wb + (size_t)r * K + k0 + kq);
            Bs[kq + 0][r] = w.x; Bs[kq + 1][r] = w.y; Bs[kq + 2][r] = w.z; Bs[kq + 3][r] = w.w;
        }
        __syncthreads();
        #pragma unroll
        for (int k = 0; k < 16; k++) {
            float ra[8], rb[8];
            #pragma unroll
            for (int i = 0; i < 8; i++) ra[i] = As[k][ty * 8 + i];
            #pragma unroll
            for (int j = 0; j < 8; j++) rb[j] = Bs[k][tx * 8 + j];
            #pragma unroll
            for (int i = 0; i < 8; i++)
                #pragma unroll
                for (int j = 0; j < 8; j++) acc[i][j] = fmaf(ra[i], rb[j], acc[i][j]);
        }
        __syncthreads();
    }
    #pragma unroll
    for (int i = 0; i < 8; i++) {
        int row = m0 + ty * 8 + i;
        #pragma unroll
        for (int j = 0; j < 8; j++) {
            int col = n0 + tx * 8 + j;
            float v = acc[i][j];
            if (EPI >= 1) v += bias[col];
            if (EPI == 2) v = 0.5f * v * (1.0f + erff(v * 0.70710678118654752f));
            if (EPI == 1) v += res[(size_t)row * N + col];
            C[(size_t)row * N + col] = v;
        }
    }
}

// ---------------- QK^T: S[b,h,i,j] = scale * q_i . k_j ----------------
__global__ void __launch_bounds__(256) qk_kernel(const float* __restrict__ qkv,
                                                 float* __restrict__ attn) {
    int z = blockIdx.z;
    int b = z / H_, h = z % H_;
    int m0 = blockIdx.y * 128, n0 = blockIdx.x * 128;
    const float* Qb = qkv + (size_t)b * N_ * C3_ + h * HD_;
    const float* Kb = Qb + C_;
    __shared__ float Qs[32][128];
    __shared__ float Ks[32][128];
    int tid = threadIdx.x;
    int ty = tid >> 4, tx = tid & 15;
    float acc[8][8] = {};
    for (int k0 = 0; k0 < HD_; k0 += 32) {
        #pragma unroll
        for (int l = 0; l < 4; l++) {
            int f = tid + l * 256;
            int r = f >> 3, kq = (f & 7) << 2;
            float4 a = *(const float4*)(Qb + (size_t)(m0 + r) * C3_ + k0 + kq);
            Qs[kq + 0][r] = a.x; Qs[kq + 1][r] = a.y; Qs[kq + 2][r] = a.z; Qs[kq + 3][r] = a.w;
            float4 kk = *(const float4*)(Kb + (size_t)(n0 + r) * C3_ + k0 + kq);
            Ks[kq + 0][r] = kk.x; Ks[kq + 1][r] = kk.y; Ks[kq + 2][r] = kk.z; Ks[kq + 3][r] = kk.w;
        }
        __syncthreads();
        #pragma unroll
        for (int k = 0; k < 32; k++) {
            float ra[8], rb[8];
            #pragma unroll
            for (int i = 0; i < 8; i++) ra[i] = Qs[k][ty * 8 + i];
            #pragma unroll
            for (int j = 0; j < 8; j++) rb[j] = Ks[k][tx * 8 + j];
            #pragma unroll
            for (int i = 0; i < 8; i++)
                #pragma unroll
                for (int j = 0; j < 8; j++) acc[i][j] = fmaf(ra[i], rb[j], acc[i][j]);
        }
        __syncthreads();
    }
    float* Cb = attn + (size_t)z * N_ * N_;
    #pragma unroll
    for (int i = 0; i < 8; i++) {
        int row = m0 + ty * 8 + i;
        #pragma unroll
        for (int j = 0; j < 8; j++) {
            Cb[(size_t)row * N_ + n0 + tx * 8 + j] = acc[i][j] * 0.125f;  // HD^-0.5
        }
    }
}

// ---------------- softmax with policy, one block (256 thr) per row of 2048 ----------------
__global__ void __launch_bounds__(256) softmax_kernel(float* __restrict__ attn,
                                                      const float* __restrict__ policy) {
    __shared__ float red[32];
    int row = blockIdx.x;            // (b*H + h)*N + i
    int b = row / (H_ * N_);
    int i = row % N_;
    float* s = attn + (size_t)row * N_;
    const float* pol = policy + (size_t)b * N_;
    int t = threadIdx.x;
    float vals[8];
    float mx = -1e30f;
    #pragma unroll
    for (int r = 0; r < 8; r++) {
        vals[r] = s[t + r * 256];
        mx = fmaxf(mx, vals[r]);
    }
    mx = block_max256(mx, red);
    float sum = 0.0f;
    #pragma unroll
    for (int r = 0; r < 8; r++) {
        int j = t + r * 256;
        float p = pol[j];
        float ap = (j == i) ? 1.0f : p;  // p + (1-p)*eye
        vals[r] = __expf(vals[r] - mx) * ap;
        sum += vals[r];
    }
    sum = block_sum256(sum, red);
    float inv = 1.0f / (sum + 1e-6f);
    const float addc = 1e-6f / (float)N_;
    #pragma unroll
    for (int r = 0; r < 8; r++) s[t + r * 256] = (vals[r] + addc) * inv;
}

// ---------------- P @ V with fused [B,H,N,D] -> [B,N,H*D] transpose ----------------
__global__ void __launch_bounds__(256) av_kernel(const float* __restrict__ attn,
                                                 const float* __restrict__ qkv,
                                                 float* __restrict__ o) {
    int z = blockIdx.y;
    int b = z / H_, h = z % H_;
    int m0 = blockIdx.x * 128;
    const float* P = attn + (size_t)z * N_ * N_;
    const float* Vb = qkv + (size_t)b * N_ * C3_ + 2 * C_ + h * HD_;
    __shared__ float Ps[32][128];
    __shared__ float Vs[32][64];
    int tid = threadIdx.x;
    int ty = tid >> 4, tx = tid & 15;
    float acc[8][4] = {};
    for (int k0 = 0; k0 < N_; k0 += 32) {
        #pragma unroll
        for (int l = 0; l < 4; l++) {
            int f = tid + l * 256;
            int r = f >> 3, kq = (f & 7) << 2;
            float4 a = *(const float4*)(P + (size_t)(m0 + r) * N_ + k0 + kq);
            Ps[kq + 0][r] = a.x; Ps[kq + 1][r] = a.y; Ps[kq + 2][r] = a.z; Ps[kq + 3][r] = a.w;
        }
        #pragma unroll
        for (int l = 0; l < 2; l++) {
            int f = tid + l * 256;
            int kk = f >> 4, d4 = (f & 15) << 2;
            float4 v = *(const float4*)(Vb + (size_t)(k0 + kk) * C3_ + d4);
            *(float4*)&Vs[kk][d4] = v;
        }
        __syncthreads();
        #pragma unroll
        for (int k = 0; k < 32; k++) {
            float ra[8], rb[4];
            #pragma unroll
            for (int i = 0; i < 8; i++) ra[i] = Ps[k][ty * 8 + i];
            #pragma unroll
            for (int j = 0; j < 4; j++) rb[j] = Vs[k][tx * 4 + j];
            #pragma unroll
            for (int i = 0; i < 8; i++)
                #pragma unroll
                for (int j = 0; j < 4; j++) acc[i][j] = fmaf(ra[i], rb[j], acc[i][j]);
        }
        __syncthreads();
    }
    #pragma unroll
    for (int i = 0; i < 8; i++) {
        int row = m0 + ty * 8 + i;
        #pragma unroll
        for (int j = 0; j < 4; j++) {
            int d = tx * 4 + j;
            o[(size_t)(b * N_ + row) * C_ + h * HD_ + d] = acc[i][j];
        }
    }
}

// ---------------- launch ----------------
extern "C" void kernel_launch(void* const* d_in, const int* in_sizes, int n_in,
                              void* d_out, int out_size) {
    const float* x      = (const float*)d_in[0];
    const float* policy = (const float*)d_in[1];
    const float* ln1_g  = (const float*)d_in[2];
    const float* ln1_b  = (const float*)d_in[3];
    const float* qkv_w  = (const float*)d_in[4];
    const float* proj_w = (const float*)d_in[5];
    const float* proj_b = (const float*)d_in[6];
    const float* ln2_g  = (const float*)d_in[7];
    const float* ln2_b  = (const float*)d_in[8];
    const float* fc1_w  = (const float*)d_in[9];
    const float* fc1_b  = (const float*)d_in[10];
    const float* fc2_w  = (const float*)d_in[11];
    const float* fc2_b  = (const float*)d_in[12];
    float* out = (float*)d_out;

    float *h, *qkv, *attn, *o, *x2, *h3;
    cudaGetSymbolAddress((void**)&h, g_h);
    cudaGetSymbolAddress((void**)&qkv, g_qkv);
    cudaGetSymbolAddress((void**)&attn, g_attn);
    cudaGetSymbolAddress((void**)&o, g_o);
    cudaGetSymbolAddress((void**)&x2, g_x2);
    cudaGetSymbolAddress((void**)&h3, g_h3);

    const int M = B_ * N_;  // 4096

    // 1. LN1
    ln_kernel<<<M, 256>>>(x, ln1_g, ln1_b, h);
    // 2. QKV = h @ qkv_w^T   [4096, 2304]
    sgemm_nt<0><<<dim3(C3_ / 128, M / 128), 256>>>(h, qkv_w, nullptr, nullptr, qkv, M, C3_, C_);
    // 3. S = scale * Q @ K^T  (per b,h)
    qk_kernel<<<dim3(N_ / 128, N_ / 128, B_ * H_), 256>>>(qkv, attn);
    // 4. policy softmax (in place)
    softmax_kernel<<<B_ * H_ * N_, 256>>>(attn, policy);
    // 5. O = P @ V, fused transpose to [B,N,H*HD]
    av_kernel<<<dim3(N_ / 128, B_ * H_), 256>>>(attn, qkv, o);
    // 6. x2 = x + O @ proj_w^T + proj_b
    sgemm_nt<1><<<dim3(C_ / 128, M / 128), 256>>>(o, proj_w, proj_b, x, x2, M, C_, C_);
    // 7. LN2
    ln_kernel<<<M, 256>>>(x2, ln2_g, ln2_b, h);
    // 8. h3 = gelu(h @ fc1_w^T + fc1_b)
    sgemm_nt<2><<<dim3(HID_ / 128, M / 128), 256>>>(h, fc1_w, fc1_b, nullptr, h3, M, HID_, C_);
    // 9. out = x2 + h3 @ fc2_w^T + fc2_b
    sgemm_nt<1><<<dim3(C_ / 128, M / 128), 256>>>(h3, fc2_w, fc2_b, x2, out, M, C_, HID_);
}

// round 3
// speedup vs baseline: 2.1854x; 2.1854x over previous
#include <cuda_runtime.h>
#include <cuda_bf16.h>
#include <math.h>
#include <stdint.h>

#define B_   2
#define N_   2048
#define C_   768
#define H_   12
#define HD_  64
#define HID_ 3072
#define C3_  (3 * C_)
#define BH_  (B_ * H_)
#define M_   (B_ * N_)   // 4096

typedef __nv_bfloat16 bf16;

// ---------------- scratch (device globals: no allocations allowed) ----------------
__device__ bf16  g_h_hi[(size_t)M_ * C_],   g_h_lo[(size_t)M_ * C_];
__device__ bf16  g_w1_hi[(size_t)C3_ * C_], g_w1_lo[(size_t)C3_ * C_];      // qkv_w
__device__ bf16  g_w2_hi[(size_t)C_ * C_],  g_w2_lo[(size_t)C_ * C_];       // proj_w
__device__ bf16  g_w3_hi[(size_t)HID_ * C_], g_w3_lo[(size_t)HID_ * C_];    // fc1_w
__device__ bf16  g_w4_hi[(size_t)C_ * HID_], g_w4_lo[(size_t)C_ * HID_];    // fc2_w
__device__ bf16  g_qkv_hi[(size_t)M_ * C3_], g_qkv_lo[(size_t)M_ * C3_];
__device__ float g_S[(size_t)BH_ * N_ * N_];                                 // logits (400MB)
__device__ bf16  g_P_hi[(size_t)BH_ * N_ * N_], g_P_lo[(size_t)BH_ * N_ * N_];
__device__ bf16  g_Vt_hi[(size_t)BH_ * HD_ * N_], g_Vt_lo[(size_t)BH_ * HD_ * N_];
__device__ bf16  g_o_hi[(size_t)M_ * C_],  g_o_lo[(size_t)M_ * C_];
__device__ float g_x2[(size_t)M_ * C_];
__device__ bf16  g_h3_hi[(size_t)M_ * HID_], g_h3_lo[(size_t)M_ * HID_];

// ---------------- helpers ----------------
__device__ __forceinline__ uint32_t smem_u32(const void* p) {
    uint32_t a;
    asm("{ .reg .u64 t; cvta.to.shared.u64 t, %1; cvt.u32.u64 %0, t; }" : "=r"(a) : "l"(p));
    return a;
}
__device__ __forceinline__ void ldm_x4(uint32_t& r0, uint32_t& r1, uint32_t& r2, uint32_t& r3,
                                       uint32_t addr) {
    asm volatile("ldmatrix.sync.aligned.m8n8.x4.shared.b16 {%0,%1,%2,%3}, [%4];"
                 : "=r"(r0), "=r"(r1), "=r"(r2), "=r"(r3) : "r"(addr));
}
__device__ __forceinline__ void mma16816(float* c, const uint32_t* a, const uint32_t* b) {
    asm volatile(
        "mma.sync.aligned.m16n8k16.row.col.f32.bf16.bf16.f32 "
        "{%0,%1,%2,%3}, {%4,%5,%6,%7}, {%8,%9}, {%0,%1,%2,%3};"
        : "+f"(c[0]), "+f"(c[1]), "+f"(c[2]), "+f"(c[3])
        : "r"(a[0]), "r"(a[1]), "r"(a[2]), "r"(a[3]), "r"(b[0]), "r"(b[1]));
}
__device__ __forceinline__ void split_store(float v, bf16* hi, bf16* lo, size_t o) {
    bf16 h = __float2bfloat16(v);
    hi[o] = h;
    lo[o] = __float2bfloat16(v - __bfloat162float(h));
}

// ================= mma.sync GEMM: D = A[M,K] @ B[N,K]^T, bf16 hi/lo 3-term =========
// KIND: 0=QKV(hi/lo out) 1=QK(scale,f32) 2=AV(hi/lo out, o layout) 3=proj(bias+res,f32)
//       4=FC1(bias+gelu,hi/lo) 5=FC2(bias+res,f32)
template <int KIND>
__global__ void __launch_bounds__(256, 2)
gemm_mma(const bf16* __restrict__ Ahi_g, const bf16* __restrict__ Alo_g,
         const bf16* __restrict__ Bhi_g, const bf16* __restrict__ Blo_g,
         const float* __restrict__ bias, const float* __restrict__ res,
         float* __restrict__ outF, bf16* __restrict__ outHi, bf16* __restrict__ outLo) {
    constexpr int NT   = (KIND == 2) ? 64 : 128;
    constexpr int KTOT = (KIND == 1) ? 64 : (KIND == 2 ? 2048 : (KIND == 5 ? 3072 : 768));
    constexpr int LDA  = (KIND == 1) ? C3_ : (KIND == 2 ? N_ : (KIND == 5 ? HID_ : C_));
    constexpr int LDB  = (KIND == 1) ? C3_ : ((KIND == 2) ? N_ : KTOT);
    constexpr int NCH  = KTOT / 64;
    constexpr int WN   = NT / 4;        // warp col width (32 or 16)
    constexpr int NTI  = WN / 8;        // n-tiles per warp (4 or 2)
    constexpr int RS   = 72;            // padded smem row stride (bf16 elems)
    // smem offsets in bf16 elems
    constexpr int AS_H = 0, AS_L = 128 * RS, BS_H = 2 * 128 * RS, BS_L = 2 * 128 * RS + NT * RS;

    extern __shared__ __align__(16) char smem_raw[];
    bf16* smem = (bf16*)smem_raw;
    float* stage = (float*)smem_raw;
    uint32_t sbase = smem_u32(smem_raw);

    int tid = threadIdx.x, wid = tid >> 5, lane = tid & 31;
    int wr = wid >> 2, wc = wid & 3;
    int m0 = blockIdx.y * 128, n0 = blockIdx.x * NT, z = blockIdx.z;

    size_t aBase, bBase;
    int bb = 0, hh = 0;
    if (KIND == 1) {
        bb = z / H_; hh = z % H_;
        aBase = (size_t)(bb * N_ + m0) * C3_ + hh * HD_;
        bBase = (size_t)(bb * N_ + n0) * C3_ + C_ + hh * HD_;
    } else if (KIND == 2) {
        bb = z / H_; hh = z % H_;
        aBase = (size_t)z * N_ * N_ + (size_t)m0 * N_;
        bBase = (size_t)z * HD_ * N_;
    } else {
        aBase = (size_t)m0 * LDA;
        bBase = (size_t)n0 * LDB;
    }

    float acc[4][NTI][4] = {};

    for (int ch = 0; ch < NCH; ++ch) {
        if (ch) __syncthreads();
        int k0 = ch * 64;
        // A tiles: 128 rows x 64 bf16, hi + lo
        #pragma unroll
        for (int l = 0; l < 4; ++l) {
            int i = tid + l * 256;
            int r = i >> 3, cq = i & 7;
            size_t off = aBase + (size_t)r * LDA + k0 + cq * 8;
            uint32_t so = (uint32_t)(r * RS + cq * 8);
            *(uint4*)(smem + AS_H + so) = *(const uint4*)(Ahi_g + off);
            *(uint4*)(smem + AS_L + so) = *(const uint4*)(Alo_g + off);
        }
        // B tiles: NT rows x 64 bf16, hi + lo
        #pragma unroll
        for (int l = 0; l < NT / 32; ++l) {
            int i = tid + l * 256;
            int r = i >> 3, cq = i & 7;
            size_t off = bBase + (size_t)r * LDB + k0 + cq * 8;
            uint32_t so = (uint32_t)(r * RS + cq * 8);
            *(uint4*)(smem + BS_H + so) = *(const uint4*)(Bhi_g + off);
            *(uint4*)(smem + BS_L + so) = *(const uint4*)(Blo_g + off);
        }
        __syncthreads();

        #pragma unroll
        for (int pass = 0; pass < 3; ++pass) {
            uint32_t aoff = (pass == 2) ? AS_L : AS_H;
            uint32_t boff = (pass == 1) ? BS_L : BS_H;
            #pragma unroll
            for (int ks = 0; ks < 4; ++ks) {
                int kk = ks * 16;
                int sub = lane >> 3, r8 = lane & 7;
                uint32_t af[4][4];
                #pragma unroll
                for (int mt = 0; mt < 4; ++mt) {
                    int row = wr * 64 + mt * 16 + (sub & 1) * 8 + r8;
                    int col = kk + (sub >> 1) * 8;
                    ldm_x4(af[mt][0], af[mt][1], af[mt][2], af[mt][3],
                           sbase + (aoff + row * RS + col) * 2);
                }
                uint32_t bfg[NTI][2];
                #pragma unroll
                for (int np = 0; np < NTI / 2; ++np) {
                    int row = wc * WN + np * 16 + (sub >> 1) * 8 + r8;
                    int col = kk + (sub & 1) * 8;
                    ldm_x4(bfg[2 * np][0], bfg[2 * np][1], bfg[2 * np + 1][0], bfg[2 * np + 1][1],
                           sbase + (boff + row * RS + col) * 2);
                }
                #pragma unroll
                for (int mt = 0; mt < 4; ++mt)
                    #pragma unroll
                    for (int nt = 0; nt < NTI; ++nt)
                        mma16816(acc[mt][nt], af[mt], bfg[nt]);
            }
        }
    }
    __syncthreads();

    // epilogue: fragments -> smem stage (128x32) -> coalesced gmem
    #pragma unroll
    for (int cb = 0; cb < NT / 32; ++cb) {
        bool part = (NT == 128) ? (wc == cb) : ((wc >> 1) == cb);
        if (part) {
            int colbase = (NT == 128) ? 0 : (wc & 1) * 16;
            #pragma unroll
            for (int mt = 0; mt < 4; ++mt)
                #pragma unroll
                for (int nt = 0; nt < NTI; ++nt)
                    #pragma unroll
                    for (int j = 0; j < 4; ++j) {
                        int row = wr * 64 + mt * 16 + (lane >> 2) + (j >> 1) * 8;
                        int col = colbase + nt * 8 + (lane & 3) * 2 + (j & 1);
                        stage[row * 33 + col] = acc[mt][nt][j];
                    }
        }
        __syncthreads();
        #pragma unroll
        for (int l = 0; l < 16; ++l) {
            int i = tid + l * 256;
            int r = i >> 5, c = i & 31;
            float v = stage[r * 33 + c];
            int gr = m0 + r, gc = n0 + cb * 32 + c;
            if (KIND == 0) {
                split_store(v, outHi, outLo, (size_t)gr * C3_ + gc);
            } else if (KIND == 1) {
                outF[(size_t)z * N_ * N_ + (size_t)gr * N_ + gc] = v * 0.125f;
            } else if (KIND == 2) {
                split_store(v, outHi, outLo, (size_t)(bb * N_ + gr) * C_ + hh * HD_ + gc);
            } else if (KIND == 3) {
                v += bias[gc] + res[(size_t)gr * C_ + gc];
                outF[(size_t)gr * C_ + gc] = v;
            } else if (KIND == 4) {
                v += bias[gc];
                v = 0.5f * v * (1.0f + erff(v * 0.70710678118654752f));
                split_store(v, outHi, outLo, (size_t)gr * HID_ + gc);
            } else {
                v += bias[gc] + res[(size_t)gr * C_ + gc];
                outF[(size_t)gr * C_ + gc] = v;
            }
        }
        __syncthreads();
    }
}

// ---------------- block reductions ----------------
__device__ __forceinline__ float block_sum256(float v, float* red) {
    #pragma unroll
    for (int o = 16; o; o >>= 1) v += __shfl_xor_sync(0xffffffffu, v, o);
    if ((threadIdx.x & 31) == 0) red[threadIdx.x >> 5] = v;
    __syncthreads();
    if (threadIdx.x < 32) {
        float t = (threadIdx.x < 8) ? red[threadIdx.x] : 0.0f;
        #pragma unroll
        for (int o = 4; o; o >>= 1) t += __shfl_xor_sync(0xffffffffu, t, o);
        if (threadIdx.x == 0) red[0] = t;
    }
    __syncthreads();
    float r = red[0];
    __syncthreads();
    return r;
}
__device__ __forceinline__ float block_max256(float v, float* red) {
    #pragma unroll
    for (int o = 16; o; o >>= 1) v = fmaxf(v, __shfl_xor_sync(0xffffffffu, v, o));
    if ((threadIdx.x & 31) == 0) red[threadIdx.x >> 5] = v;
    __syncthreads();
    if (threadIdx.x < 32) {
        float t = (threadIdx.x < 8) ? red[threadIdx.x] : -1e30f;
        #pragma unroll
        for (int o = 4; o; o >>= 1) t = fmaxf(t, __shfl_xor_sync(0xffffffffu, t, o));
        if (threadIdx.x == 0) red[0] = t;
    }
    __syncthreads();
    float r = red[0];
    __syncthreads();
    return r;
}

// ---------------- LayerNorm -> bf16 hi/lo ----------------
__global__ void __launch_bounds__(256) ln_kernel(const float* __restrict__ x,
                                                 const float* __restrict__ g,
                                                 const float* __restrict__ b,
                                                 bf16* __restrict__ ohi,
                                                 bf16* __restrict__ olo) {
    __shared__ float red[32];
    int row = blockIdx.x;
    const float* xr = x + (size_t)row * C_;
    int t = threadIdx.x;
    float v0 = xr[t], v1 = xr[t + 256], v2 = xr[t + 512];
    float mean = block_sum256(v0 + v1 + v2, red) * (1.0f / C_);
    float d0 = v0 - mean, d1 = v1 - mean, d2 = v2 - mean;
    float var = block_sum256(d0 * d0 + d1 * d1 + d2 * d2, red) * (1.0f / C_);
    float rstd = rsqrtf(var + 1e-5f);
    size_t o = (size_t)row * C_;
    split_store(d0 * rstd * g[t]       + b[t],       ohi, olo, o + t);
    split_store(d1 * rstd * g[t + 256] + b[t + 256], ohi, olo, o + t + 256);
    split_store(d2 * rstd * g[t + 512] + b[t + 512], ohi, olo, o + t + 512);
}

// ---------------- fp32 -> bf16 hi/lo convert ----------------
__global__ void __launch_bounds__(256) cvt_kernel(const float* __restrict__ in,
                                                  bf16* __restrict__ hi,
                                                  bf16* __restrict__ lo, int n) {
    for (int i = blockIdx.x * 256 + threadIdx.x; i < n; i += gridDim.x * 256)
        split_store(in[i], hi, lo, i);
}

// ---------------- softmax with policy: S fp32 -> P bf16 hi/lo ----------------
__global__ void __launch_bounds__(256) softmax_kernel(const float* __restrict__ S,
                                                      const float* __restrict__ policy,
                                                      bf16* __restrict__ Phi,
                                                      bf16* __restrict__ Plo) {
    __shared__ float red[32];
    int row = blockIdx.x;  // (b*H + h)*N + i
    int b = row / (H_ * N_);
    int i = row % N_;
    const float* s = S + (size_t)row * N_;
    const float* pol = policy + (size_t)b * N_;
    int t = threadIdx.x;
    float vals[8];
    float mx = -1e30f;
    #pragma unroll
    for (int r = 0; r < 8; r++) { vals[r] = s[t + r * 256]; mx = fmaxf(mx, vals[r]); }
    mx = block_max256(mx, red);
    float sum = 0.0f;
    #pragma unroll
    for (int r = 0; r < 8; r++) {
        int j = t + r * 256;
        float p = pol[j];
        float ap = (j == i) ? 1.0f : p;
        vals[r] = __expf(vals[r] - mx) * ap;
        sum += vals[r];
    }
    sum = block_sum256(sum, red);
    float inv = 1.0f / (sum + 1e-6f);
    const float addc = 1e-6f / (float)N_;
    size_t o = (size_t)row * N_;
    #pragma unroll
    for (int r = 0; r < 8; r++)
        split_store((vals[r] + addc) * inv, Phi, Plo, o + t + r * 256);
}

// ---------------- V transpose: qkv[b, j, 2C + h*64 + d] -> Vt[z, d, j] ----------------
__global__ void __launch_bounds__(256) vt_kernel(const bf16* __restrict__ qhi,
                                                 const bf16* __restrict__ qlo,
                                                 bf16* __restrict__ vthi,
                                                 bf16* __restrict__ vtlo) {
    __shared__ bf16 sh[HD_][130];
    __shared__ bf16 sl[HD_][130];
    int j0 = blockIdx.x * 128, z = blockIdx.y;
    int b = z / H_, h = z % H_;
    size_t base = (size_t)(b * N_ + j0) * C3_ + 2 * C_ + h * HD_;
    for (int i = threadIdx.x; i < 128 * HD_; i += 256) {
        int d = i & 63, j = i >> 6;
        size_t off = base + (size_t)j * C3_ + d;
        sh[d][j] = qhi[off];
        sl[d][j] = qlo[off];
    }
    __syncthreads();
    size_t obase = ((size_t)z * HD_) * N_ + j0;
    for (int i = threadIdx.x; i < HD_ * 128; i += 256) {
        int j = i & 127, d = i >> 7;
        vthi[obase + (size_t)d * N_ + j] = sh[d][j];
        vtlo[obase + (size_t)d * N_ + j] = sl[d][j];
    }
}

// ---------------- launch ----------------
extern "C" void kernel_launch(void* const* d_in, const int* in_sizes, int n_in,
                              void* d_out, int out_size) {
    const float* x      = (const float*)d_in[0];
    const float* policy = (const float*)d_in[1];
    const float* ln1_g  = (const float*)d_in[2];
    const float* ln1_b  = (const float*)d_in[3];
    const float* qkv_w  = (const float*)d_in[4];
    const float* proj_w = (const float*)d_in[5];
    const float* proj_b = (const float*)d_in[6];
    const float* ln2_g  = (const float*)d_in[7];
    const float* ln2_b  = (const float*)d_in[8];
    const float* fc1_w  = (const float*)d_in[9];
    const float* fc1_b  = (const float*)d_in[10];
    const float* fc2_w  = (const float*)d_in[11];
    const float* fc2_b  = (const float*)d_in[12];
    float* out = (float*)d_out;

    bf16 *h_hi, *h_lo, *w1h, *w1l, *w2h, *w2l, *w3h, *w3l, *w4h, *w4l;
    bf16 *qh, *ql, *Ph, *Pl, *vth, *vtl, *oh, *ol, *h3h, *h3l;
    float *S, *x2;
    cudaGetSymbolAddress((void**)&h_hi, g_h_hi);  cudaGetSymbolAddress((void**)&h_lo, g_h_lo);
    cudaGetSymbolAddress((void**)&w1h, g_w1_hi);  cudaGetSymbolAddress((void**)&w1l, g_w1_lo);
    cudaGetSymbolAddress((void**)&w2h, g_w2_hi);  cudaGetSymbolAddress((void**)&w2l, g_w2_lo);
    cudaGetSymbolAddress((void**)&w3h, g_w3_hi);  cudaGetSymbolAddress((void**)&w3l, g_w3_lo);
    cudaGetSymbolAddress((void**)&w4h, g_w4_hi);  cudaGetSymbolAddress((void**)&w4l, g_w4_lo);
    cudaGetSymbolAddress((void**)&qh, g_qkv_hi);  cudaGetSymbolAddress((void**)&ql, g_qkv_lo);
    cudaGetSymbolAddress((void**)&S, g_S);
    cudaGetSymbolAddress((void**)&Ph, g_P_hi);    cudaGetSymbolAddress((void**)&Pl, g_P_lo);
    cudaGetSymbolAddress((void**)&vth, g_Vt_hi);  cudaGetSymbolAddress((void**)&vtl, g_Vt_lo);
    cudaGetSymbolAddress((void**)&oh, g_o_hi);    cudaGetSymbolAddress((void**)&ol, g_o_lo);
    cudaGetSymbolAddress((void**)&x2, g_x2);
    cudaGetSymbolAddress((void**)&h3h, g_h3_hi);  cudaGetSymbolAddress((void**)&h3l, g_h3_lo);

    const int RS = 72;
    const int SMEM_BIG = (2 * 128 * RS + 2 * 128 * RS) * 2;  // 73728
    const int SMEM_AV  = (2 * 128 * RS + 2 * 64 * RS) * 2;   // 55296
    cudaFuncSetAttribute(gemm_mma<0>, cudaFuncAttributeMaxDynamicSharedMemorySize, SMEM_BIG);
    cudaFuncSetAttribute(gemm_mma<1>, cudaFuncAttributeMaxDynamicSharedMemorySize, SMEM_BIG);
    cudaFuncSetAttribute(gemm_mma<2>, cudaFuncAttributeMaxDynamicSharedMemorySize, SMEM_AV);
    cudaFuncSetAttribute(gemm_mma<3>, cudaFuncAttributeMaxDynamicSharedMemorySize, SMEM_BIG);
    cudaFuncSetAttribute(gemm_mma<4>, cudaFuncAttributeMaxDynamicSharedMemorySize, SMEM_BIG);
    cudaFuncSetAttribute(gemm_mma<5>, cudaFuncAttributeMaxDynamicSharedMemorySize, SMEM_BIG);

    // weights -> bf16 hi/lo
    cvt_kernel<<<2048, 256>>>(qkv_w,  w1h, w1l, C3_ * C_);
    cvt_kernel<<<2048, 256>>>(proj_w, w2h, w2l, C_ * C_);
    cvt_kernel<<<2048, 256>>>(fc1_w,  w3h, w3l, HID_ * C_);
    cvt_kernel<<<2048, 256>>>(fc2_w,  w4h, w4l, C_ * HID_);
    // LN1
    ln_kernel<<<M_, 256>>>(x, ln1_g, ln1_b, h_hi, h_lo);
    // QKV
    gemm_mma<0><<<dim3(C3_ / 128, M_ / 128, 1), 256, SMEM_BIG>>>(
        h_hi, h_lo, w1h, w1l, nullptr, nullptr, nullptr, qh, ql);
    // V transpose
    vt_kernel<<<dim3(N_ / 128, BH_), 256>>>(qh, ql, vth, vtl);
    // S = scale * Q K^T
    gemm_mma<1><<<dim3(N_ / 128, N_ / 128, BH_), 256, SMEM_BIG>>>(
        qh, ql, qh, ql, nullptr, nullptr, S, nullptr, nullptr);
    // policy softmax -> P hi/lo
    softmax_kernel<<<BH_ * N_, 256>>>(S, policy, Ph, Pl);
    // O = P V  (fused transpose to [B,N,H*HD] via epilogue)
    gemm_mma<2><<<dim3(1, N_ / 128, BH_), 256, SMEM_AV>>>(
        Ph, Pl, vth, vtl, nullptr, nullptr, nullptr, oh, ol);
    // x2 = x + O proj_w^T + proj_b
    gemm_mma<3><<<dim3(C_ / 128, M_ / 128, 1), 256, SMEM_BIG>>>(
        oh, ol, w2h, w2l, proj_b, x, x2, nullptr, nullptr);
    // LN2
    ln_kernel<<<M_, 256>>>(x2, ln2_g, ln2_b, h_hi, h_lo);
    // h3 = gelu(h fc1_w^T + fc1_b)
    gemm_mma<4><<<dim3(HID_ / 128, M_ / 128, 1), 256, SMEM_BIG>>>(
        h_hi, h_lo, w3h, w3l, fc1_b, nullptr, nullptr, h3h, h3l);
    // out = x2 + h3 fc2_w^T + fc2_b
    gemm_mma<5><<<dim3(C_ / 128, M_ / 128, 1), 256, SMEM_BIG>>>(
        h3h, h3l, w4h, w4l, fc2_b, x2, out, nullptr, nullptr);
}

// round 5
// speedup vs baseline: 2.5651x; 1.1737x over previous
#include <cuda_runtime.h>
#include <cuda_bf16.h>
#include <math.h>
#include <stdint.h>

#define B_   2
#define N_   2048
#define C_   768
#define H_   12
#define HD_  64
#define HID_ 3072
#define C3_  (3 * C_)
#define BH_  (B_ * H_)
#define M_   (B_ * N_)   // 4096

typedef __nv_bfloat16 bf16;

// ---------------- scratch (device globals: no allocations allowed) ----------------
__device__ bf16  g_h_hi[(size_t)M_ * C_],   g_h_lo[(size_t)M_ * C_];
__device__ bf16  g_w1_hi[(size_t)C3_ * C_], g_w1_lo[(size_t)C3_ * C_];
__device__ bf16  g_w2_hi[(size_t)C_ * C_],  g_w2_lo[(size_t)C_ * C_];
__device__ bf16  g_w3_hi[(size_t)HID_ * C_], g_w3_lo[(size_t)HID_ * C_];
__device__ bf16  g_w4_hi[(size_t)C_ * HID_], g_w4_lo[(size_t)C_ * HID_];
__device__ bf16  g_qkv_hi[(size_t)M_ * C3_], g_qkv_lo[(size_t)M_ * C3_];
__device__ bf16  g_Vt_hi[(size_t)BH_ * HD_ * N_], g_Vt_lo[(size_t)BH_ * HD_ * N_];
__device__ float g_sumV[(size_t)BH_ * HD_];
__device__ bf16  g_o_hi[(size_t)M_ * C_],  g_o_lo[(size_t)M_ * C_];
__device__ float g_x2[(size_t)M_ * C_];
__device__ bf16  g_h3_hi[(size_t)M_ * HID_], g_h3_lo[(size_t)M_ * HID_];

// ---------------- helpers ----------------
__device__ __forceinline__ uint32_t smem_u32(const void* p) {
    uint32_t a;
    asm("{ .reg .u64 t; cvta.to.shared.u64 t, %1; cvt.u32.u64 %0, t; }" : "=r"(a) : "l"(p));
    return a;
}
__device__ __forceinline__ void ldm_x4(uint32_t& r0, uint32_t& r1, uint32_t& r2, uint32_t& r3,
                                       uint32_t addr) {
    asm volatile("ldmatrix.sync.aligned.m8n8.x4.shared.b16 {%0,%1,%2,%3}, [%4];"
                 : "=r"(r0), "=r"(r1), "=r"(r2), "=r"(r3) : "r"(addr));
}
__device__ __forceinline__ void mma16816(float* c, const uint32_t* a, const uint32_t* b) {
    asm volatile(
        "mma.sync.aligned.m16n8k16.row.col.f32.bf16.bf16.f32 "
        "{%0,%1,%2,%3}, {%4,%5,%6,%7}, {%8,%9}, {%0,%1,%2,%3};"
        : "+f"(c[0]), "+f"(c[1]), "+f"(c[2]), "+f"(c[3])
        : "r"(a[0]), "r"(a[1]), "r"(a[2]), "r"(a[3]), "r"(b[0]), "r"(b[1]));
}
__device__ __forceinline__ void split_store(float v, bf16* hi, bf16* lo, size_t o) {
    bf16 h = __float2bfloat16(v);
    hi[o] = h;
    lo[o] = __float2bfloat16(v - __bfloat162float(h));
}
__device__ __forceinline__ uint32_t pack_bf(float v0, float v1) {
    __nv_bfloat162 p(__float2bfloat16(v0), __float2bfloat16(v1));
    return *(uint32_t*)&p;
}
__device__ __forceinline__ float bf_hi_f(float v) {
    return __bfloat162float(__float2bfloat16(v));
}

// ================= dense mma GEMM: D = A[M,K] @ B[N,K]^T, bf16 hi/lo 3-term =========
// KIND: 0=QKV(hi/lo out) 3=proj(bias+res,f32) 4=FC1(bias+gelu,hi/lo) 5=FC2(bias+res,f32)
template <int KIND>
__global__ void __launch_bounds__(256, 2)
gemm_mma(const bf16* __restrict__ Ahi_g, const bf16* __restrict__ Alo_g,
         const bf16* __restrict__ Bhi_g, const bf16* __restrict__ Blo_g,
         const float* __restrict__ bias, const float* __restrict__ res,
         float* __restrict__ outF, bf16* __restrict__ outHi, bf16* __restrict__ outLo) {
    constexpr int KTOT = (KIND == 5) ? 3072 : 768;
    constexpr int LDA  = (KIND == 5) ? HID_ : C_;
    constexpr int LDB  = KTOT;
    constexpr int NCH  = KTOT / 64;
    constexpr int RS   = 72;
    constexpr int AS_H = 0, AS_L = 128 * RS, BS_H = 2 * 128 * RS, BS_L = 3 * 128 * RS;

    extern __shared__ __align__(16) char smem_raw[];
    bf16* smem = (bf16*)smem_raw;
    float* stage = (float*)smem_raw;
    uint32_t sbase = smem_u32(smem_raw);

    int tid = threadIdx.x, wid = tid >> 5, lane = tid & 31;
    int wr = wid >> 2, wc = wid & 3;
    int m0 = blockIdx.y * 128, n0 = blockIdx.x * 128;

    size_t aBase = (size_t)m0 * LDA;
    size_t bBase = (size_t)n0 * LDB;

    float acc[4][4][4] = {};

    for (int ch = 0; ch < NCH; ++ch) {
        if (ch) __syncthreads();
        int k0 = ch * 64;
        #pragma unroll
        for (int l = 0; l < 4; ++l) {
            int i = tid + l * 256;
            int r = i >> 3, cq = i & 7;
            size_t off = aBase + (size_t)r * LDA + k0 + cq * 8;
            uint32_t so = (uint32_t)(r * RS + cq * 8);
            *(uint4*)(smem + AS_H + so) = *(const uint4*)(Ahi_g + off);
            *(uint4*)(smem + AS_L + so) = *(const uint4*)(Alo_g + off);
        }
        #pragma unroll
        for (int l = 0; l < 4; ++l) {
            int i = tid + l * 256;
            int r = i >> 3, cq = i & 7;
            size_t off = bBase + (size_t)r * LDB + k0 + cq * 8;
            uint32_t so = (uint32_t)(r * RS + cq * 8);
            *(uint4*)(smem + BS_H + so) = *(const uint4*)(Bhi_g + off);
            *(uint4*)(smem + BS_L + so) = *(const uint4*)(Blo_g + off);
        }
        __syncthreads();

        #pragma unroll
        for (int pass = 0; pass < 3; ++pass) {
            uint32_t aoff = (pass == 2) ? AS_L : AS_H;
            uint32_t boff = (pass == 1) ? BS_L : BS_H;
            #pragma unroll
            for (int ks = 0; ks < 4; ++ks) {
                int kk = ks * 16;
                int sub = lane >> 3, r8 = lane & 7;
                uint32_t af[4][4];
                #pragma unroll
                for (int mt = 0; mt < 4; ++mt) {
                    int row = wr * 64 + mt * 16 + (sub & 1) * 8 + r8;
                    int col = kk + (sub >> 1) * 8;
                    ldm_x4(af[mt][0], af[mt][1], af[mt][2], af[mt][3],
                           sbase + (aoff + row * RS + col) * 2);
                }
                uint32_t bfg[4][2];
                #pragma unroll
                for (int np = 0; np < 2; ++np) {
                    int row = wc * 32 + np * 16 + (sub >> 1) * 8 + r8;
                    int col = kk + (sub & 1) * 8;
                    ldm_x4(bfg[2 * np][0], bfg[2 * np][1], bfg[2 * np + 1][0], bfg[2 * np + 1][1],
                           sbase + (boff + row * RS + col) * 2);
                }
                #pragma unroll
                for (int mt = 0; mt < 4; ++mt)
                    #pragma unroll
                    for (int nt = 0; nt < 4; ++nt)
                        mma16816(acc[mt][nt], af[mt], bfg[nt]);
            }
        }
    }
    __syncthreads();

    #pragma unroll
    for (int cb = 0; cb < 4; ++cb) {
        if (wc == cb) {
            #pragma unroll
            for (int mt = 0; mt < 4; ++mt)
                #pragma unroll
                for (int nt = 0; nt < 4; ++nt)
                    #pragma unroll
                    for (int j = 0; j < 4; ++j) {
                        int row = wr * 64 + mt * 16 + (lane >> 2) + (j >> 1) * 8;
                        int col = nt * 8 + (lane & 3) * 2 + (j & 1);
                        stage[row * 33 + col] = acc[mt][nt][j];
                    }
        }
        __syncthreads();
        #pragma unroll
        for (int l = 0; l < 16; ++l) {
            int i = tid + l * 256;
            int r = i >> 5, c = i & 31;
            float v = stage[r * 33 + c];
            int gr = m0 + r, gc = n0 + cb * 32 + c;
            if (KIND == 0) {
                split_store(v, outHi, outLo, (size_t)gr * C3_ + gc);
            } else if (KIND == 3) {
                v += bias[gc] + res[(size_t)gr * C_ + gc];
                outF[(size_t)gr * C_ + gc] = v;
            } else if (KIND == 4) {
                v += bias[gc];
                v = 0.5f * v * (1.0f + erff(v * 0.70710678118654752f));
                split_store(v, outHi, outLo, (size_t)gr * HID_ + gc);
            } else {
                v += bias[gc] + res[(size_t)gr * C_ + gc];
                outF[(size_t)gr * C_ + gc] = v;
            }
        }
        __syncthreads();
    }
}

// ================= flash attention with policy softmax =================
// One CTA per (z = b*H+h, 128-query tile). 8 warps, each owns 16 query rows.
__global__ void __launch_bounds__(256)
flash_kernel(const bf16* __restrict__ qkvh, const bf16* __restrict__ qkvl,
             const bf16* __restrict__ vth, const bf16* __restrict__ vtl,
             const float* __restrict__ policy, const float* __restrict__ sumV,
             bf16* __restrict__ ohi, bf16* __restrict__ olo) {
    constexpr int RS = 72, VS = 136;
    constexpr int QH = 0, QL = 128 * RS, KH = 2 * 128 * RS, KL = 3 * 128 * RS;
    constexpr int VTH = 4 * 128 * RS, VTL = VTH + 64 * VS;
    constexpr int POLO = VTL + 64 * VS;  // bf16-elem offset; *2 = byte offset (16B-aligned)

    extern __shared__ __align__(16) char smem_raw[];
    bf16* sm = (bf16*)smem_raw;
    float* pol = (float*)(smem_raw + (size_t)POLO * 2);
    uint32_t sbase = smem_u32(smem_raw);

    int tid = threadIdx.x, wid = tid >> 5, lane = tid & 31;
    int m0 = blockIdx.x * 128, z = blockIdx.y;
    int b = z / H_, h = z % H_;
    int sub = lane >> 3, r8 = lane & 7;
    int gi0 = m0 + wid * 16 + (lane >> 2), gi1 = gi0 + 8;

    // Q tile (persistent)
    #pragma unroll
    for (int l = 0; l < 4; ++l) {
        int i = tid + l * 256;
        int r = i >> 3, cq = i & 7;
        size_t off = (size_t)(b * N_ + m0 + r) * C3_ + h * HD_ + cq * 8;
        uint32_t so = (uint32_t)(r * RS + cq * 8);
        *(uint4*)(sm + QH + so) = *(const uint4*)(qkvh + off);
        *(uint4*)(sm + QL + so) = *(const uint4*)(qkvl + off);
    }

    float m_r0 = -1e30f, m_r1 = -1e30f, l_r0 = 0.0f, l_r1 = 0.0f;
    float accO[8][4] = {};

    for (int j0 = 0; j0 < N_; j0 += 128) {
        __syncthreads();
        // K chunk
        #pragma unroll
        for (int l = 0; l < 4; ++l) {
            int i = tid + l * 256;
            int r = i >> 3, cq = i & 7;
            size_t off = (size_t)(b * N_ + j0 + r) * C3_ + C_ + h * HD_ + cq * 8;
            uint32_t so = (uint32_t)(r * RS + cq * 8);
            *(uint4*)(sm + KH + so) = *(const uint4*)(qkvh + off);
            *(uint4*)(sm + KL + so) = *(const uint4*)(qkvl + off);
        }
        // Vt chunk [64 d][128 j]
        #pragma unroll
        for (int l = 0; l < 4; ++l) {
            int i = tid + l * 256;
            int d = i >> 4, cq = i & 15;
            size_t off = ((size_t)z * HD_ + d) * N_ + j0 + cq * 8;
            uint32_t so = (uint32_t)(d * VS + cq * 8);
            *(uint4*)(sm + VTH + so) = *(const uint4*)(vth + off);
            *(uint4*)(sm + VTL + so) = *(const uint4*)(vtl + off);
        }
        if (tid < 128) pol[tid] = policy[(size_t)b * N_ + j0 + tid];
        __syncthreads();

        // ---- S = Q K^T (16 rows x 128 cols per warp), hi/lo 3-term ----
        float sacc[16][4] = {};
        #pragma unroll
        for (int pass = 0; pass < 3; ++pass) {
            uint32_t ao = (pass == 2) ? QL : QH;
            uint32_t bo = (pass == 1) ? KL : KH;
            #pragma unroll
            for (int ks = 0; ks < 4; ++ks) {
                int kk = ks * 16;
                uint32_t af[4];
                {
                    int row = wid * 16 + (sub & 1) * 8 + r8;
                    int col = kk + (sub >> 1) * 8;
                    ldm_x4(af[0], af[1], af[2], af[3], sbase + (ao + row * RS + col) * 2);
                }
                uint32_t bfg[16][2];
                #pragma unroll
                for (int np = 0; np < 8; ++np) {
                    int row = np * 16 + (sub >> 1) * 8 + r8;
                    int col = kk + (sub & 1) * 8;
                    ldm_x4(bfg[2 * np][0], bfg[2 * np][1], bfg[2 * np + 1][0], bfg[2 * np + 1][1],
                           sbase + (bo + row * RS + col) * 2);
                }
                #pragma unroll
                for (int nt = 0; nt < 16; ++nt) mma16816(sacc[nt], af, bfg[nt]);
            }
        }

        // ---- online policy softmax update ----
        float cm0 = -1e30f, cm1 = -1e30f;
        #pragma unroll
        for (int nt = 0; nt < 16; ++nt) {
            cm0 = fmaxf(cm0, fmaxf(sacc[nt][0], sacc[nt][1]));
            cm1 = fmaxf(cm1, fmaxf(sacc[nt][2], sacc[nt][3]));
        }
        cm0 *= 0.125f; cm1 *= 0.125f;
        #pragma unroll
        for (int o = 1; o < 4; o <<= 1) {
            cm0 = fmaxf(cm0, __shfl_xor_sync(0xffffffffu, cm0, o));
            cm1 = fmaxf(cm1, __shfl_xor_sync(0xffffffffu, cm1, o));
        }
        float mn0 = fmaxf(m_r0, cm0), mn1 = fmaxf(m_r1, cm1);
        float fac0 = __expf(m_r0 - mn0), fac1 = __expf(m_r1 - mn1);
        m_r0 = mn0; m_r1 = mn1;
        float cs0 = 0.0f, cs1 = 0.0f;
        #pragma unroll
        for (int nt = 0; nt < 16; ++nt) {
            int jl = 8 * nt + 2 * (lane & 3);
            int jg = j0 + jl;
            float p0 = pol[jl], p1 = pol[jl + 1];
            float e0 = __expf(sacc[nt][0] * 0.125f - mn0) * ((jg == gi0) ? 1.0f : p0);
            float e1 = __expf(sacc[nt][1] * 0.125f - mn0) * ((jg + 1 == gi0) ? 1.0f : p1);
            float e2 = __expf(sacc[nt][2] * 0.125f - mn1) * ((jg == gi1) ? 1.0f : p0);
            float e3 = __expf(sacc[nt][3] * 0.125f - mn1) * ((jg + 1 == gi1) ? 1.0f : p1);
            sacc[nt][0] = e0; sacc[nt][1] = e1; sacc[nt][2] = e2; sacc[nt][3] = e3;
            cs0 += e0 + e1; cs1 += e2 + e3;
        }
        #pragma unroll
        for (int o = 1; o < 4; o <<= 1) {
            cs0 += __shfl_xor_sync(0xffffffffu, cs0, o);
            cs1 += __shfl_xor_sync(0xffffffffu, cs1, o);
        }
        l_r0 = l_r0 * fac0 + cs0;
        l_r1 = l_r1 * fac1 + cs1;
        #pragma unroll
        for (int nt = 0; nt < 8; ++nt) {
            accO[nt][0] *= fac0; accO[nt][1] *= fac0;
            accO[nt][2] *= fac1; accO[nt][3] *= fac1;
        }

        // ---- O += P @ V  (P repacked from sacc fragments; hi/lo 3-term) ----
        #pragma unroll
        for (int kt = 0; kt < 8; ++kt) {
            uint32_t ah[4], al[4];
            {
                float v00 = sacc[2 * kt][0],     v01 = sacc[2 * kt][1];
                float v02 = sacc[2 * kt][2],     v03 = sacc[2 * kt][3];
                float v10 = sacc[2 * kt + 1][0], v11 = sacc[2 * kt + 1][1];
                float v12 = sacc[2 * kt + 1][2], v13 = sacc[2 * kt + 1][3];
                ah[0] = pack_bf(v00, v01); ah[1] = pack_bf(v02, v03);
                ah[2] = pack_bf(v10, v11); ah[3] = pack_bf(v12, v13);
                al[0] = pack_bf(v00 - bf_hi_f(v00), v01 - bf_hi_f(v01));
                al[1] = pack_bf(v02 - bf_hi_f(v02), v03 - bf_hi_f(v03));
                al[2] = pack_bf(v10 - bf_hi_f(v10), v11 - bf_hi_f(v11));
                al[3] = pack_bf(v12 - bf_hi_f(v12), v13 - bf_hi_f(v13));
            }
            #pragma unroll
            for (int ntb = 0; ntb < 4; ++ntb) {
                int row = ntb * 16 + (sub >> 1) * 8 + r8;
                int col = kt * 16 + (sub & 1) * 8;
                uint32_t bh0[2], bh1[2], bl0[2], bl1[2];
                ldm_x4(bh0[0], bh0[1], bh1[0], bh1[1], sbase + (VTH + row * VS + col) * 2);
                ldm_x4(bl0[0], bl0[1], bl1[0], bl1[1], sbase + (VTL + row * VS + col) * 2);
                mma16816(accO[2 * ntb],     ah, bh0);
                mma16816(accO[2 * ntb + 1], ah, bh1);
                mma16816(accO[2 * ntb],     ah, bl0);
                mma16816(accO[2 * ntb + 1], ah, bl1);
                mma16816(accO[2 * ntb],     al, bh0);
                mma16816(accO[2 * ntb + 1], al, bh1);
            }
        }
    }

    // ---- epilogue: O = (accO + addc*sumV) / (l + eps), write hi/lo bf16 ----
    float inv0 = 1.0f / (l_r0 + 1e-6f), inv1 = 1.0f / (l_r1 + 1e-6f);
    const float addc = 1e-6f / (float)N_;
    #pragma unroll
    for (int nt = 0; nt < 8; ++nt) {
        int d = 8 * nt + 2 * (lane & 3);
        float sv0 = sumV[(size_t)z * HD_ + d], sv1 = sumV[(size_t)z * HD_ + d + 1];
        float o00 = (accO[nt][0] + addc * sv0) * inv0;
        float o01 = (accO[nt][1] + addc * sv1) * inv0;
        float o10 = (accO[nt][2] + addc * sv0) * inv1;
        float o11 = (accO[nt][3] + addc * sv1) * inv1;
        size_t off0 = (size_t)(b * N_ + gi0) * C_ + h * HD_ + d;
        size_t off1 = (size_t)(b * N_ + gi1) * C_ + h * HD_ + d;
        __nv_bfloat162 h0(__float2bfloat16(o00), __float2bfloat16(o01));
        __nv_bfloat162 h1(__float2bfloat16(o10), __float2bfloat16(o11));
        *(__nv_bfloat162*)(ohi + off0) = h0;
        *(__nv_bfloat162*)(ohi + off1) = h1;
        __nv_bfloat162 l0(__float2bfloat16(o00 - __bfloat162float(h0.x)),
                          __float2bfloat16(o01 - __bfloat162float(h0.y)));
        __nv_bfloat162 l1(__float2bfloat16(o10 - __bfloat162float(h1.x)),
                          __float2bfloat16(o11 - __bfloat162float(h1.y)));
        *(__nv_bfloat162*)(olo + off0) = l0;
        *(__nv_bfloat162*)(olo + off1) = l1;
    }
}

// ---------------- block reductions ----------------
__device__ __forceinline__ float block_sum256(float v, float* red) {
    #pragma unroll
    for (int o = 16; o; o >>= 1) v += __shfl_xor_sync(0xffffffffu, v, o);
    if ((threadIdx.x & 31) == 0) red[threadIdx.x >> 5] = v;
    __syncthreads();
    if (threadIdx.x < 32) {
        float t = (threadIdx.x < 8) ? red[threadIdx.x] : 0.0f;
        #pragma unroll
        for (int o = 4; o; o >>= 1) t += __shfl_xor_sync(0xffffffffu, t, o);
        if (threadIdx.x == 0) red[0] = t;
    }
    __syncthreads();
    float r = red[0];
    __syncthreads();
    return r;
}

// ---------------- LayerNorm -> bf16 hi/lo ----------------
__global__ void __launch_bounds__(256) ln_kernel(const float* __restrict__ x,
                                                 const float* __restrict__ g,
                                                 const float* __restrict__ b,
                                                 bf16* __restrict__ ohi,
                                                 bf16* __restrict__ olo) {
    __shared__ float red[32];
    int row = blockIdx.x;
    const float* xr = x + (size_t)row * C_;
    int t = threadIdx.x;
    float v0 = xr[t], v1 = xr[t + 256], v2 = xr[t + 512];
    float mean = block_sum256(v0 + v1 + v2, red) * (1.0f / C_);
    float d0 = v0 - mean, d1 = v1 - mean, d2 = v2 - mean;
    float var = block_sum256(d0 * d0 + d1 * d1 + d2 * d2, red) * (1.0f / C_);
    float rstd = rsqrtf(var + 1e-5f);
    size_t o = (size_t)row * C_;
    split_store(d0 * rstd * g[t]       + b[t],       ohi, olo, o + t);
    split_store(d1 * rstd * g[t + 256] + b[t + 256], ohi, olo, o + t + 256);
    split_store(d2 * rstd * g[t + 512] + b[t + 512], ohi, olo, o + t + 512);
}

// ---------------- fp32 -> bf16 hi/lo convert ----------------
__global__ void __launch_bounds__(256) cvt_kernel(const float* __restrict__ in,
                                                  bf16* __restrict__ hi,
                                                  bf16* __restrict__ lo, int n) {
    for (int i = blockIdx.x * 256 + threadIdx.x; i < n; i += gridDim.x * 256)
        split_store(in[i], hi, lo, i);
}

// ---------------- V transpose: qkv[b, j, 2C + h*64 + d] -> Vt[z, d, j] ----------------
__global__ void __launch_bounds__(256) vt_kernel(const bf16* __restrict__ qhi,
                                                 const bf16* __restrict__ qlo,
                                                 bf16* __restrict__ vthi,
                                                 bf16* __restrict__ vtlo) {
    __shared__ bf16 sh[HD_][130];
    __shared__ bf16 sl[HD_][130];
    int j0 = blockIdx.x * 128, z = blockIdx.y;
    int b = z / H_, h = z % H_;
    size_t base = (size_t)(b * N_ + j0) * C3_ + 2 * C_ + h * HD_;
    for (int i = threadIdx.x; i < 128 * HD_; i += 256) {
        int d = i & 63, j = i >> 6;
        size_t off = base + (size_t)j * C3_ + d;
        sh[d][j] = qhi[off];
        sl[d][j] = qlo[off];
    }
    __syncthreads();
    size_t obase = ((size_t)z * HD_) * N_ + j0;
    for (int i = threadIdx.x; i < HD_ * 128; i += 256) {
        int j = i & 127, d = i >> 7;
        vthi[obase + (size_t)d * N_ + j] = sh[d][j];
        vtlo[obase + (size_t)d * N_ + j] = sl[d][j];
    }
}

// ---------------- sumV[z][d] = sum_j V[z,j,d] ----------------
__global__ void __launch_bounds__(1024) sumv_kernel(const bf16* __restrict__ qhi,
                                                    const bf16* __restrict__ qlo,
                                                    float* __restrict__ sumV) {
    __shared__ float red[16][65];
    int z = blockIdx.x;
    int b = z / H_, h = z % H_;
    int d = threadIdx.x & 63, part = threadIdx.x >> 6;  // 16 parts x 128 j
    float s = 0.0f;
    for (int j = part * 128; j < part * 128 + 128; ++j) {
        size_t off = (size_t)(b * N_ + j) * C3_ + 2 * C_ + h * HD_ + d;
        s += __bfloat162float(qhi[off]) + __bfloat162float(qlo[off]);
    }
    red[part][d] = s;
    __syncthreads();
    if (part == 0) {
        float t = 0.0f;
        #pragma unroll
        for (int p = 0; p < 16; ++p) t += red[p][d];
        sumV[(size_t)z * HD_ + d] = t;
    }
}

// ---------------- launch ----------------
extern "C" void kernel_launch(void* const* d_in, const int* in_sizes, int n_in,
                              void* d_out, int out_size) {
    const float* x      = (const float*)d_in[0];
    const float* policy = (const float*)d_in[1];
    const float* ln1_g  = (const float*)d_in[2];
    const float* ln1_b  = (const float*)d_in[3];
    const float* qkv_w  = (const float*)d_in[4];
    const float* proj_w = (const float*)d_in[5];
    const float* proj_b = (const float*)d_in[6];
    const float* ln2_g  = (const float*)d_in[7];
    const float* ln2_b  = (const float*)d_in[8];
    const float* fc1_w  = (const float*)d_in[9];
    const float* fc1_b  = (const float*)d_in[10];
    const float* fc2_w  = (const float*)d_in[11];
    const float* fc2_b  = (const float*)d_in[12];
    float* out = (float*)d_out;

    bf16 *h_hi, *h_lo, *w1h, *w1l, *w2h, *w2l, *w3h, *w3l, *w4h, *w4l;
    bf16 *qh, *ql, *vth, *vtl, *oh, *ol, *h3h, *h3l;
    float *x2, *sumV;
    cudaGetSymbolAddress((void**)&h_hi, g_h_hi);  cudaGetSymbolAddress((void**)&h_lo, g_h_lo);
    cudaGetSymbolAddress((void**)&w1h, g_w1_hi);  cudaGetSymbolAddress((void**)&w1l, g_w1_lo);
    cudaGetSymbolAddress((void**)&w2h, g_w2_hi);  cudaGetSymbolAddress((void**)&w2l, g_w2_lo);
    cudaGetSymbolAddress((void**)&w3h, g_w3_hi);  cudaGetSymbolAddress((void**)&w3l, g_w3_lo);
    cudaGetSymbolAddress((void**)&w4h, g_w4_hi);  cudaGetSymbolAddress((void**)&w4l, g_w4_lo);
    cudaGetSymbolAddress((void**)&qh, g_qkv_hi);  cudaGetSymbolAddress((void**)&ql, g_qkv_lo);
    cudaGetSymbolAddress((void**)&vth, g_Vt_hi);  cudaGetSymbolAddress((void**)&vtl, g_Vt_lo);
    cudaGetSymbolAddress((void**)&oh, g_o_hi);    cudaGetSymbolAddress((void**)&ol, g_o_lo);
    cudaGetSymbolAddress((void**)&x2, g_x2);
    cudaGetSymbolAddress((void**)&h3h, g_h3_hi);  cudaGetSymbolAddress((void**)&h3l, g_h3_lo);
    cudaGetSymbolAddress((void**)&sumV, g_sumV);

    const int RS = 72, VS = 136;
    const int SMEM_GEMM = (4 * 128 * RS) * 2;                       // 73728
    const int SMEM_FLASH = (4 * 128 * RS + 2 * 64 * VS) * 2 + 512;  // 109056
    cudaFuncSetAttribute(gemm_mma<0>, cudaFuncAttributeMaxDynamicSharedMemorySize, SMEM_GEMM);
    cudaFuncSetAttribute(gemm_mma<3>, cudaFuncAttributeMaxDynamicSharedMemorySize, SMEM_GEMM);
    cudaFuncSetAttribute(gemm_mma<4>, cudaFuncAttributeMaxDynamicSharedMemorySize, SMEM_GEMM);
    cudaFuncSetAttribute(gemm_mma<5>, cudaFuncAttributeMaxDynamicSharedMemorySize, SMEM_GEMM);
    cudaFuncSetAttribute(flash_kernel, cudaFuncAttributeMaxDynamicSharedMemorySize, SMEM_FLASH);

    // weights -> bf16 hi/lo
    cvt_kernel<<<2048, 256>>>(qkv_w,  w1h, w1l, C3_ * C_);
    cvt_kernel<<<2048, 256>>>(proj_w, w2h, w2l, C_ * C_);
    cvt_kernel<<<2048, 256>>>(fc1_w,  w3h, w3l, HID_ * C_);
    cvt_kernel<<<2048, 256>>>(fc2_w,  w4h, w4l, C_ * HID_);
    // LN1
    ln_kernel<<<M_, 256>>>(x, ln1_g, ln1_b, h_hi, h_lo);
    // QKV
    gemm_mma<0><<<dim3(C3_ / 128, M_ / 128), 256, SMEM_GEMM>>>(
        h_hi, h_lo, w1h, w1l, nullptr, nullptr, nullptr, qh, ql);
    // V transpose + V column sums
    vt_kernel<<<dim3(N_ / 128, BH_), 256>>>(qh, ql, vth, vtl);
    sumv_kernel<<<BH_, 1024>>>(qh, ql, sumV);
    // flash attention (QK^T + policy softmax + PV fused)
    flash_kernel<<<dim3(N_ / 128, BH_), 256, SMEM_FLASH>>>(
        qh, ql, vth, vtl, policy, sumV, oh, ol);
    // x2 = x + O proj_w^T + proj_b
    gemm_mma<3><<<dim3(C_ / 128, M_ / 128), 256, SMEM_GEMM>>>(
        oh, ol, w2h, w2l, proj_b, x, x2, nullptr, nullptr);
    // LN2
    ln_kernel<<<M_, 256>>>(x2, ln2_g, ln2_b, h_hi, h_lo);
    // h3 = gelu(h fc1_w^T + fc1_b)
    gemm_mma<4><<<dim3(HID_ / 128, M_ / 128), 256, SMEM_GEMM>>>(
        h_hi, h_lo, w3h, w3l, fc1_b, nullptr, nullptr, h3h, h3l);
    // out = x2 + h3 fc2_w^T + fc2_b
    gemm_mma<5><<<dim3(C_ / 128, M_ / 128), 256, SMEM_GEMM>>>(
        h3h, h3l, w4h, w4l, fc2_b, x2, out, nullptr, nullptr);
}